// round 10
// baseline (speedup 1.0000x reference)
#include <cuda_runtime.h>

#define WFULL 0xFFFFFFFFu

// Deterministic fixed-point accumulator (integer adds are associative).
__device__ unsigned long long g_acc = 0ULL;
__device__ unsigned int g_ticket = 0u;

// Delete-chain affine scan for TWO independent element-pairs, interleaved.
// 4 states/lane, 16-lane segments. fD[k] = aMD[k-1]*fM[k-1] + aDD[k-1]*fD[k-1].
__device__ __forceinline__ void d_scan4_x2(
    const float aMD[2][4], const float dd[2][4], const float Ds[2][4],
    const float M[2][4], int hl, float D[2][4], float D64[2])
{
    float c[2][4], C[2];
    #pragma unroll
    for (int p = 0; p < 2; ++p) {
        c[p][0] = aMD[p][0] * M[p][0];
        c[p][1] = aMD[p][1] * M[p][1];
        c[p][2] = aMD[p][2] * M[p][2];
        c[p][3] = aMD[p][3] * M[p][3];
        float t = fmaf(dd[p][1], c[p][0], c[p][1]);
        t = fmaf(dd[p][2], t, c[p][2]);
        C[p] = fmaf(dd[p][3], t, c[p][3]);
    }
    {
        float u0 = __shfl_up_sync(WFULL, C[0], 1, 16);
        float u1 = __shfl_up_sync(WFULL, C[1], 1, 16);
        if (hl >= 1) { C[0] = fmaf(Ds[0][0], u0, C[0]); C[1] = fmaf(Ds[1][0], u1, C[1]); }
        u0 = __shfl_up_sync(WFULL, C[0], 2, 16);
        u1 = __shfl_up_sync(WFULL, C[1], 2, 16);
        if (hl >= 2) { C[0] = fmaf(Ds[0][1], u0, C[0]); C[1] = fmaf(Ds[1][1], u1, C[1]); }
        u0 = __shfl_up_sync(WFULL, C[0], 4, 16);
        u1 = __shfl_up_sync(WFULL, C[1], 4, 16);
        if (hl >= 4) { C[0] = fmaf(Ds[0][2], u0, C[0]); C[1] = fmaf(Ds[1][2], u1, C[1]); }
        u0 = __shfl_up_sync(WFULL, C[0], 8, 16);
        u1 = __shfl_up_sync(WFULL, C[1], 8, 16);
        if (hl >= 8) { C[0] = fmaf(Ds[0][3], u0, C[0]); C[1] = fmaf(Ds[1][3], u1, C[1]); }
    }
    float P0 = __shfl_up_sync(WFULL, C[0], 1, 16);
    float P1 = __shfl_up_sync(WFULL, C[1], 1, 16);
    if (hl == 0) { P0 = 0.f; P1 = 0.f; }
    D[0][0] = P0;
    D[1][0] = P1;
    #pragma unroll
    for (int p = 0; p < 2; ++p) {
        D[p][1] = fmaf(dd[p][0], D[p][0], c[p][0]);
        D[p][2] = fmaf(dd[p][1], D[p][1], c[p][1]);
        D[p][3] = fmaf(dd[p][2], D[p][2], c[p][2]);
    }
    D64[0] = C[0];
    D64[1] = C[1];
}

__global__ __launch_bounds__(32)
void phmm_ilp2_kernel(const int*   __restrict__ x,
                      const float* __restrict__ tp,   // (B,65,7)
                      const float* __restrict__ ep,   // (B,64,4)
                      const float* __restrict__ mus,  // (B,16)
                      const float* __restrict__ lvs,  // (B,16)
                      float* __restrict__ out, int B)
{
    __shared__ float4 es_sm[2][4][32];   // [pair][sym][lane] (warp-private block)

    const int lane = threadIdx.x;        // block = 1 warp
    const int hl   = lane & 15;          // lane within 16-lane segment
    const int e    = lane >> 4;          // element within a pair
    const int base = blockIdx.x * 4;
    const int k0   = hl * 4;

    float aMM[2][4], aMIq[2][4], aMD[2][4], aIM[2][4], aIIq[2][4], aDM[2][4], dd[2][4], Ds[2][4];
    float aMI64q[2], aII64q[2];
    float M[2][4], I[2][4], D[2][4], M64[2], I64[2], D64[2];
    unsigned xpk[2];
    int bidx[2]; bool val[2];

    #pragma unroll
    for (int p = 0; p < 2; ++p) {
        int b = base + p * 2 + e;
        val[p] = (b < B);
        if (!val[p]) b = B - 1;          // clamp for safe loads
        bidx[p] = b;

        // transitions (exp once): M2M,M2I,M2D,I2M,I2I,D2M,D2D
        const float* a = tp + ((size_t)b * 65 + k0) * 7;
        #pragma unroll
        for (int j = 0; j < 4; ++j) {
            aMM[p][j]  = __expf(a[7 * j + 0]);
            aMIq[p][j] = 0.25f * __expf(a[7 * j + 1]);   // fold LOG_Q = log(1/4)
            aMD[p][j]  = __expf(a[7 * j + 2]);
            aIM[p][j]  = __expf(a[7 * j + 3]);
            aIIq[p][j] = 0.25f * __expf(a[7 * j + 4]);
            aDM[p][j]  = __expf(a[7 * j + 5]);
            dd[p][j]   = __expf(a[7 * j + 6]);
        }
        aMI64q[p] = 0.f; aII64q[p] = 0.f;   // zero on hl!=15 -> I64 stays 0 there
        if (hl == 15) {
            const float* a64 = tp + ((size_t)b * 65 + 64) * 7;
            aMI64q[p] = 0.25f * __expf(a64[1]);
            aII64q[p] = 0.25f * __expf(a64[4]);
        }

        // emissions -> per-thread SMEM table (written & read by same thread)
        {
            const float4* e4 = (const float4*)(ep + ((size_t)b * 64 + k0) * 4);
            const float4 f0 = e4[0], f1 = e4[1], f2 = e4[2], f3 = e4[3];
            es_sm[p][0][lane] = make_float4(__expf(f0.x), __expf(f1.x), __expf(f2.x), __expf(f3.x));
            es_sm[p][1][lane] = make_float4(__expf(f0.y), __expf(f1.y), __expf(f2.y), __expf(f3.y));
            es_sm[p][2][lane] = make_float4(__expf(f0.z), __expf(f1.z), __expf(f2.z), __expf(f3.z));
            es_sm[p][3][lane] = make_float4(__expf(f0.w), __expf(f1.w), __expf(f2.w), __expf(f3.w));
        }

        // symbol stream: 8 symbols per lane, 2-bit packed
        {
            const int4* x4 = (const int4*)(x + (size_t)b * 128);
            const int4 xa = x4[2 * hl], xb = x4[2 * hl + 1];
            xpk[p] = (unsigned)xa.x | ((unsigned)xa.y << 2) | ((unsigned)xa.z << 4) | ((unsigned)xa.w << 6)
                   | ((unsigned)xb.x << 8) | ((unsigned)xb.y << 10) | ((unsigned)xb.z << 12) | ((unsigned)xb.w << 14);
        }

        // constant multiplicative scan factors
        {
            float Dc = dd[p][0] * dd[p][1] * dd[p][2] * dd[p][3];
            float u;
            Ds[p][0] = Dc; u = __shfl_up_sync(WFULL, Dc, 1, 16); if (hl >= 1) Dc *= u;
            Ds[p][1] = Dc; u = __shfl_up_sync(WFULL, Dc, 2, 16); if (hl >= 2) Dc *= u;
            Ds[p][2] = Dc; u = __shfl_up_sync(WFULL, Dc, 4, 16); if (hl >= 4) Dc *= u;
            Ds[p][3] = Dc;
        }

        // initial state: fM[0]=1, rest ~0 (exp(-100) ~ 0)
        M[p][0] = (hl == 0) ? 1.0f : 0.0f;
        M[p][1] = 0.f; M[p][2] = 0.f; M[p][3] = 0.f;
        I[p][0] = 0.f; I[p][1] = 0.f; I[p][2] = 0.f; I[p][3] = 0.f;
        M64[p] = 0.f; I64[p] = 0.f; D64[p] = 0.f;
    }

    d_scan4_x2(aMD, dd, Ds, M, hl, D, D64);

    int ez[2] = {0, 0};

    #pragma unroll 1
    for (int g = 0; g < 32; ++g) {
        const unsigned w0 = __shfl_sync(WFULL, xpk[0], g >> 1, 16);
        const unsigned w1 = __shfl_sync(WFULL, xpk[1], g >> 1, 16);
        const unsigned bits0 = w0 >> ((g & 1) * 8);   // 4 syms x 2 bits
        const unsigned bits1 = w1 >> ((g & 1) * 8);

        #pragma unroll
        for (int j = 0; j < 4; ++j) {
            const float4 esv0 = es_sm[0][(bits0 >> (2 * j)) & 3u][lane];
            const float4 esv1 = es_sm[1][(bits1 >> (2 * j)) & 3u][lane];
            float m3v[2];
            #pragma unroll
            for (int p = 0; p < 2; ++p) {
                const float4 es = p ? esv1 : esv0;
                const float m0 = es.x * fmaf(aMM[p][0], M[p][0], fmaf(aIM[p][0], I[p][0], aDM[p][0] * D[p][0]));
                const float m1 = es.y * fmaf(aMM[p][1], M[p][1], fmaf(aIM[p][1], I[p][1], aDM[p][1] * D[p][1]));
                const float m2 = es.z * fmaf(aMM[p][2], M[p][2], fmaf(aIM[p][2], I[p][2], aDM[p][2] * D[p][2]));
                const float m3 = es.w * fmaf(aMM[p][3], M[p][3], fmaf(aIM[p][3], I[p][3], aDM[p][3] * D[p][3]));
                const float nI64 = fmaf(aMI64q[p], M64[p], aII64q[p] * I64[p]);   // OLD M64
                I[p][0] = fmaf(aMIq[p][0], M[p][0], aIIq[p][0] * I[p][0]);
                I[p][1] = fmaf(aMIq[p][1], M[p][1], aIIq[p][1] * I[p][1]);
                I[p][2] = fmaf(aMIq[p][2], M[p][2], aIIq[p][2] * I[p][2]);
                I[p][3] = fmaf(aMIq[p][3], M[p][3], aIIq[p][3] * I[p][3]);
                M64[p] = m3;            // fM[64] on hl==15; harmless elsewhere
                I64[p] = nI64;
                M[p][1] = m0; M[p][2] = m1; M[p][3] = m2;
                m3v[p] = m3;
            }
            const float sh0 = __shfl_up_sync(WFULL, m3v[0], 1, 16);
            const float sh1 = __shfl_up_sync(WFULL, m3v[1], 1, 16);
            M[0][0] = (hl == 0) ? 0.f : sh0;   // fM_new[0] = exp(NEG) ~ 0
            M[1][0] = (hl == 0) ? 0.f : sh1;
            d_scan4_x2(aMD, dd, Ds, M, hl, D, D64);
        }

        // power-of-2 rescale once per 4 steps (exact; no MUFU)
        float mx0 = fmaxf(fmaxf(fmaxf(M[0][0], M[0][1]), fmaxf(M[0][2], M[0][3])),
                          fmaxf(fmaxf(I[0][0], I[0][1]), fmaxf(I[0][2], I[0][3])));
        float mx1 = fmaxf(fmaxf(fmaxf(M[1][0], M[1][1]), fmaxf(M[1][2], M[1][3])),
                          fmaxf(fmaxf(I[1][0], I[1][1]), fmaxf(I[1][2], I[1][3])));
        mx0 = fmaxf(mx0, fmaxf(M64[0], I64[0]));
        mx1 = fmaxf(mx1, fmaxf(M64[1], I64[1]));
        #pragma unroll
        for (int k = 8; k >= 1; k >>= 1) {
            const float u0 = __shfl_xor_sync(WFULL, mx0, k, 16);
            const float u1 = __shfl_xor_sync(WFULL, mx1, k, 16);
            mx0 = fmaxf(mx0, u0);
            mx1 = fmaxf(mx1, u1);
        }
        const int eb0 = (__float_as_int(mx0) >> 23) - 127;
        const int eb1 = (__float_as_int(mx1) >> 23) - 127;
        const float sc0 = __int_as_float((127 - eb0) << 23);   // exact 2^(-eb)
        const float sc1 = __int_as_float((127 - eb1) << 23);
        ez[0] += eb0; ez[1] += eb1;
        #pragma unroll
        for (int j = 0; j < 4; ++j) {
            M[0][j] *= sc0; I[0][j] *= sc0; D[0][j] *= sc0;
            M[1][j] *= sc1; I[1][j] *= sc1; D[1][j] *= sc1;
        }
        M64[0] *= sc0; I64[0] *= sc0; D64[0] *= sc0;
        M64[1] *= sc1; I64[1] *= sc1; D64[1] *= sc1;
    }

    // ---- KLD + final, per pair ----
    long long my[2] = {0LL, 0LL};
    #pragma unroll
    for (int p = 0; p < 2; ++p) {
        const float mu = mus[(size_t)bidx[p] * 16 + hl];
        const float lv = lvs[(size_t)bidx[p] * 16 + hl];
        float kt = 1.0f + lv - mu * mu - __expf(lv);
        kt += __shfl_xor_sync(WFULL, kt, 8, 16);
        kt += __shfl_xor_sync(WFULL, kt, 4, 16);
        kt += __shfl_xor_sync(WFULL, kt, 2, 16);
        kt += __shfl_xor_sync(WFULL, kt, 1, 16);
        if (hl == 15) {
            const float* a64 = tp + ((size_t)bidx[p] * 65 + 64) * 7;
            const float aMM64 = __expf(a64[0]);
            const float aIM64 = __expf(a64[3]);
            const float aDM64 = __expf(a64[5]);
            float fin = fmaf(aMM64, M64[p], fmaf(aIM64, I64[p], aDM64 * D64[p]));
            fin = fmaxf(fin, 1.4e-45f);
            const float recon = -(__logf(fin) + 0.69314718055994530942f * (float)ez[p]);
            const float loss = recon - 0.5f * kt;
            my[p] = val[p] ? llrintf(loss * 67108864.0f) : 0LL;   // fixed point 2^26
        }
    }

    // ---- deterministic warp + grid reduction (1 warp per block) ----
    long long tot = __shfl_sync(WFULL, my[0], 15) + __shfl_sync(WFULL, my[0], 31)
                  + __shfl_sync(WFULL, my[1], 15) + __shfl_sync(WFULL, my[1], 31);
    if (lane == 0) {
        atomicAdd(&g_acc, (unsigned long long)tot);
        __threadfence();
        const unsigned int t = atomicAdd(&g_ticket, 1u);
        if (t == gridDim.x - 1) {
            const long long sum = (long long)atomicAdd(&g_acc, 0ULL);
            out[0] = (float)((double)sum / (67108864.0 * (double)B));
            g_acc = 0ULL;     // reset for next graph replay
            g_ticket = 0u;
        }
    }
}

extern "C" void kernel_launch(void* const* d_in, const int* in_sizes, int n_in,
                              void* d_out, int out_size)
{
    const int*   x   = (const int*)d_in[0];
    const float* tp  = (const float*)d_in[1];
    const float* ep  = (const float*)d_in[2];
    const float* mus = (const float*)d_in[3];
    const float* lvs = (const float*)d_in[4];
    float* out = (float*)d_out;

    int B = in_sizes[0] / 128;
    if (B > 4096) B = 4096;
    const int blocks = (B + 3) / 4;   // 4 batch elements per 1-warp block

    phmm_ilp2_kernel<<<blocks, 32>>>(x, tp, ep, mus, lvs, out, B);
}